// round 3
// baseline (speedup 1.0000x reference)
#include <cuda_runtime.h>
#include <cuda_bf16.h>
#include <math.h>

// Problem constants
#define N1 8
#define N2 8
#define P  1024
#define D  768
#define PH 32
#define PW 32
#define OH 512
#define OW 512

// Scratch (no cudaMalloc allowed) — kernels reference these globals directly.
__device__ float g_F[N1 * P * D];        // normalized feats
__device__ float g_G[N2 * P * D];        // normalized nfeats
__device__ float g_spatch[N1 * N2 * P];  // scores_patch[n][m][p]
__device__ float g_sp[N1 * P];           // mean over m, (n, 32*32)

// ---------------------------------------------------------------------------
// Kernel 1: row-normalize. grid = 16384 rows, block = 192 (768/4 float4s)
// ---------------------------------------------------------------------------
__global__ void norm_k(const float* __restrict__ feats,
                       const float* __restrict__ nfeats) {
    int row = blockIdx.x;
    const float* src;
    float* dst;
    if (row < N1 * P) {
        src = feats + (size_t)row * D;
        dst = g_F + (size_t)row * D;
    } else {
        int r = row - N1 * P;
        src = nfeats + (size_t)r * D;
        dst = g_G + (size_t)r * D;
    }
    int t = threadIdx.x;  // 0..191
    float4 x = *(const float4*)(src + t * 4);
    float s = x.x * x.x + x.y * x.y + x.z * x.z + x.w * x.w;
    #pragma unroll
    for (int off = 16; off; off >>= 1)
        s += __shfl_xor_sync(0xffffffffu, s, off);
    __shared__ float ws[6];
    __shared__ float rnorm_s;
    if ((t & 31) == 0) ws[t >> 5] = s;
    __syncthreads();
    if (t == 0) {
        float tot = 0.f;
        #pragma unroll
        for (int i = 0; i < 6; i++) tot += ws[i];
        rnorm_s = 1.0f / sqrtf(tot);
    }
    __syncthreads();
    float r = rnorm_s;
    float4 o;
    o.x = x.x * r; o.y = x.y * r; o.z = x.z * r; o.w = x.w * r;
    *(float4*)(dst + t * 4) = o;
}

// ---------------------------------------------------------------------------
// Kernel 2: fused batched GEMM + max over q.
// For pair (n,m): C[p,q] = f_n[p,:].g_m[q,:]; running max over q per p;
// epilogue: spatch = 0.5*sqrt(max(2-2*cmax,0)) (unit rows => fa2=gb2=1).
// BM=128 (p tile), q looped in BN=128 chunks, BK=16. 256 threads, 8x8 micro.
// grid = (P/128 = 8, 64 pairs)
// ---------------------------------------------------------------------------
#define BM 128
#define BN 128
#define BK 16

__global__ __launch_bounds__(256, 2)
void gemm_max_k() {
    __shared__ float As[BK][BM];
    __shared__ float Bs[BK][BN];

    const int pair = blockIdx.y;
    const int n = pair >> 3;
    const int m = pair & 7;
    const int p0 = blockIdx.x * BM;
    const float* __restrict__ Fb = g_F + (size_t)n * P * D;
    const float* __restrict__ Gb = g_G + (size_t)m * P * D;

    const int tid = threadIdx.x;
    const int tx = tid & 15;        // q micro-tile index
    const int ty = tid >> 4;        // p micro-tile index
    const int lr = tid >> 2;        // 0..63 : load row within half-tile
    const int lc = (tid & 3) * 4;   // 0,4,8,12 : load col (float4)

    float cmax[8];
    #pragma unroll
    for (int i = 0; i < 8; i++) cmax[i] = -1e30f;

    for (int q0 = 0; q0 < P; q0 += BN) {
        float acc[8][8];
        #pragma unroll
        for (int i = 0; i < 8; i++)
            #pragma unroll
            for (int j = 0; j < 8; j++) acc[i][j] = 0.f;

        for (int k0 = 0; k0 < D; k0 += BK) {
            float4 a0 = *(const float4*)(Fb + (p0 + lr) * D + k0 + lc);
            float4 a1 = *(const float4*)(Fb + (p0 + 64 + lr) * D + k0 + lc);
            float4 b0 = *(const float4*)(Gb + (q0 + lr) * D + k0 + lc);
            float4 b1 = *(const float4*)(Gb + (q0 + 64 + lr) * D + k0 + lc);
            __syncthreads();  // previous-iter smem reads complete
            As[lc + 0][lr] = a0.x; As[lc + 1][lr] = a0.y;
            As[lc + 2][lr] = a0.z; As[lc + 3][lr] = a0.w;
            As[lc + 0][64 + lr] = a1.x; As[lc + 1][64 + lr] = a1.y;
            As[lc + 2][64 + lr] = a1.z; As[lc + 3][64 + lr] = a1.w;
            Bs[lc + 0][lr] = b0.x; Bs[lc + 1][lr] = b0.y;
            Bs[lc + 2][lr] = b0.z; Bs[lc + 3][lr] = b0.w;
            Bs[lc + 0][64 + lr] = b1.x; Bs[lc + 1][64 + lr] = b1.y;
            Bs[lc + 2][64 + lr] = b1.z; Bs[lc + 3][64 + lr] = b1.w;
            __syncthreads();

            #pragma unroll
            for (int k = 0; k < BK; k++) {
                float a[8], b[8];
                *(float4*)(a)     = *(const float4*)&As[k][ty * 8];
                *(float4*)(a + 4) = *(const float4*)&As[k][ty * 8 + 4];
                *(float4*)(b)     = *(const float4*)&Bs[k][tx * 8];
                *(float4*)(b + 4) = *(const float4*)&Bs[k][tx * 8 + 4];
                #pragma unroll
                for (int i = 0; i < 8; i++)
                    #pragma unroll
                    for (int j = 0; j < 8; j++)
                        acc[i][j] = fmaf(a[i], b[j], acc[i][j]);
            }
        }
        #pragma unroll
        for (int i = 0; i < 8; i++)
            #pragma unroll
            for (int j = 0; j < 8; j++)
                cmax[i] = fmaxf(cmax[i], acc[i][j]);
    }

    // Reduce max over the 16 tx-threads (contiguous 16-lane groups in warp)
    #pragma unroll
    for (int i = 0; i < 8; i++) {
        float v = cmax[i];
        #pragma unroll
        for (int off = 8; off; off >>= 1)
            v = fmaxf(v, __shfl_xor_sync(0xffffffffu, v, off));
        cmax[i] = v;
    }
    if (tx == 0) {
        #pragma unroll
        for (int i = 0; i < 8; i++) {
            int p = p0 + ty * 8 + i;
            float d2 = fmaxf(2.0f - 2.0f * cmax[i], 0.0f);
            g_spatch[(size_t)pair * P + p] = 0.5f * sqrtf(d2);
        }
    }
}

// ---------------------------------------------------------------------------
// Kernel 3: scores[n] = mean_m max_p spatch; sp[n][p] = mean_m spatch.
// grid = 8, block = 1024 (one thread per p)
// ---------------------------------------------------------------------------
__global__ void reduce_k(float* __restrict__ scores) {
    const int n = blockIdx.x;
    const int p = threadIdx.x;
    float v[8];
    float s = 0.f;
    #pragma unroll
    for (int m = 0; m < 8; m++) {
        v[m] = g_spatch[(size_t)(n * 8 + m) * P + p];
        s += v[m];
    }
    g_sp[n * P + p] = s * 0.125f;

    __shared__ int smax[8];
    if (p < 8) smax[p] = 0;  // dist >= 0 so int-compare == float-compare
    __syncthreads();
    #pragma unroll
    for (int m = 0; m < 8; m++) {
        float x = v[m];
        #pragma unroll
        for (int off = 16; off; off >>= 1)
            x = fmaxf(x, __shfl_xor_sync(0xffffffffu, x, off));
        if ((p & 31) == 0) atomicMax(&smax[m], __float_as_int(x));
    }
    __syncthreads();
    if (p == 0) {
        float t = 0.f;
        #pragma unroll
        for (int m = 0; m < 8; m++) t += __int_as_float(smax[m]);
        scores[n] = t * 0.125f;
    }
}

// ---------------------------------------------------------------------------
// Kernel 4: bilinear resize (8,32,32) -> (8,512,512)
// ---------------------------------------------------------------------------
__global__ void resize_k(float* __restrict__ out) {
    int idx = blockIdx.x * blockDim.x + threadIdx.x;
    if (idx >= N1 * OH * OW) return;
    int c = idx & (OW - 1);
    int r = (idx >> 9) & (OH - 1);
    int n = idx >> 18;
    float sy = (r + 0.5f) * ((float)PH / OH) - 0.5f;
    float sx = (c + 0.5f) * ((float)PW / OW) - 0.5f;
    float y0f = floorf(sy), x0f = floorf(sx);
    float wy = sy - y0f, wx = sx - x0f;
    int y0 = min(max((int)y0f, 0), PH - 1);
    int y1 = min(max((int)y0f + 1, 0), PH - 1);
    int x0 = min(max((int)x0f, 0), PW - 1);
    int x1 = min(max((int)x0f + 1, 0), PW - 1);
    const float* b = g_sp + n * (PH * PW);
    float v00 = b[y0 * PW + x0], v01 = b[y0 * PW + x1];
    float v10 = b[y1 * PW + x0], v11 = b[y1 * PW + x1];
    float top = v00 * (1.f - wx) + v01 * wx;
    float bot = v10 * (1.f - wx) + v11 * wx;
    out[idx] = top * (1.f - wy) + bot * wy;
}

// ---------------------------------------------------------------------------
extern "C" void kernel_launch(void* const* d_in, const int* in_sizes, int n_in,
                              void* d_out, int out_size) {
    (void)in_sizes; (void)n_in; (void)out_size;
    const float* feats  = (const float*)d_in[0];
    const float* nfeats = (const float*)d_in[1];
    float* out = (float*)d_out;  // [0..7] = scores, [8..] = scores_pixel

    norm_k<<<(N1 + N2) * P, 192>>>(feats, nfeats);
    dim3 ggrid(P / BM, N1 * N2);
    gemm_max_k<<<ggrid, 256>>>();
    reduce_k<<<N1, P>>>(out);
    resize_k<<<(N1 * OH * OW + 255) / 256, 256>>>(out + N1);
}

// round 5
// speedup vs baseline: 7.0528x; 7.0528x over previous
#include <cuda_runtime.h>
#include <cuda_bf16.h>
#include <math.h>
#include <stdint.h>

// Problem constants
#define N1 8
#define N2 8
#define P  1024
#define D  768
#define PH 32
#define PW 32
#define OH 512
#define OW 512

// GEMM tiling
#define BM 128
#define BN 128
#define BK 32
#define STAGES 3
#define KSTEPS (D / BK)           // 24
#define QSTEPS (P / BN)           // 8
#define NSTEP  (KSTEPS * QSTEPS)  // 192
#define TILE_BYTES  8192          // 128 rows * 32 bf16 * 2B
#define STAGE_BYTES (2 * TILE_BYTES)

// Scratch (no cudaMalloc allowed)
__device__ __nv_bfloat16 g_Fh[N1 * P * D];  // normalized feats, bf16
__device__ __nv_bfloat16 g_Gh[N2 * P * D];  // normalized nfeats, bf16
__device__ float g_spatch[N1 * N2 * P];     // scores_patch[n][m][p]
__device__ float g_sp[N1 * P];              // mean over m

// ---------------------------------------------------------------------------
// Helpers
// ---------------------------------------------------------------------------
__device__ __forceinline__ uint32_t cvta_s(const void* p) {
    return (uint32_t)__cvta_generic_to_shared(p);
}

#define CPA16(dst, src) \
    asm volatile("cp.async.cg.shared.global [%0], [%1], 16;\n" :: "r"(dst), "l"(src))
#define CPA_COMMIT() asm volatile("cp.async.commit_group;\n" ::: "memory")
#define CPA_WAIT1()  asm volatile("cp.async.wait_group 1;\n" ::: "memory")

__device__ __forceinline__ void ldsm4(uint32_t& r0, uint32_t& r1, uint32_t& r2,
                                      uint32_t& r3, uint32_t a) {
    asm volatile("ldmatrix.sync.aligned.m8n8.x4.shared.b16 {%0,%1,%2,%3}, [%4];\n"
                 : "=r"(r0), "=r"(r1), "=r"(r2), "=r"(r3) : "r"(a));
}

__device__ __forceinline__ void mma16816(float* c, const uint32_t* a, const uint32_t* b) {
    asm volatile(
        "mma.sync.aligned.m16n8k16.row.col.f32.bf16.bf16.f32 "
        "{%0,%1,%2,%3}, {%4,%5,%6,%7}, {%8,%9}, {%0,%1,%2,%3};\n"
        : "+f"(c[0]), "+f"(c[1]), "+f"(c[2]), "+f"(c[3])
        : "r"(a[0]), "r"(a[1]), "r"(a[2]), "r"(a[3]), "r"(b[0]), "r"(b[1]));
}

// Tile row = 32 bf16 = 64B = 4 chunks of 16B. XOR swizzle: conflict-free
// ldmatrix (8 rows at fixed logical chunk hit 8 distinct 16B slots mod 128B).
__device__ __forceinline__ uint32_t swaddr(int row, int ch) {
    return (uint32_t)((row << 6) | (((ch ^ ((row >> 1) & 3)) & 3) << 4));
}

// ---------------------------------------------------------------------------
// Kernel 1: row-normalize -> bf16. grid = 16384 rows, block = 192
// ---------------------------------------------------------------------------
__global__ void norm_k(const float* __restrict__ feats,
                       const float* __restrict__ nfeats) {
    int row = blockIdx.x;
    const float* src;
    __nv_bfloat16* dst;
    if (row < N1 * P) {
        src = feats + (size_t)row * D;
        dst = g_Fh + (size_t)row * D;
    } else {
        int r = row - N1 * P;
        src = nfeats + (size_t)r * D;
        dst = g_Gh + (size_t)r * D;
    }
    int t = threadIdx.x;  // 0..191
    float4 x = *(const float4*)(src + t * 4);
    float s = x.x * x.x + x.y * x.y + x.z * x.z + x.w * x.w;
    #pragma unroll
    for (int off = 16; off; off >>= 1)
        s += __shfl_xor_sync(0xffffffffu, s, off);
    __shared__ float ws[6];
    __shared__ float rnorm_s;
    if ((t & 31) == 0) ws[t >> 5] = s;
    __syncthreads();
    if (t == 0) {
        float tot = 0.f;
        #pragma unroll
        for (int i = 0; i < 6; i++) tot += ws[i];
        rnorm_s = 1.0f / sqrtf(tot);
    }
    __syncthreads();
    float r = rnorm_s;
    __nv_bfloat162 h0 = __floats2bfloat162_rn(x.x * r, x.y * r);
    __nv_bfloat162 h1 = __floats2bfloat162_rn(x.z * r, x.w * r);
    uint2 pk;
    pk.x = *(uint32_t*)&h0;
    pk.y = *(uint32_t*)&h1;
    *(uint2*)(dst + t * 4) = pk;
}

// ---------------------------------------------------------------------------
// Kernel 2: bf16 tensor-core batched GEMM + running max over q.
// grid = (P/BM = 8, 64 pairs), 256 threads = 8 warps (2 m-rows x 4 n-cols),
// warp tile 64m x 32n, mma.m16n8k16, 3-stage cp.async pipeline.
// ---------------------------------------------------------------------------
__global__ __launch_bounds__(256, 2)
void gemm_max_k() {
    __shared__ __align__(1024) unsigned char smem[STAGES * STAGE_BYTES];  // 48KB
    const uint32_t sbase = cvta_s(smem);

    const int pair = blockIdx.y;
    const __nv_bfloat16* __restrict__ Fb = g_Fh + (size_t)(pair >> 3) * P * D;
    const __nv_bfloat16* __restrict__ Gb = g_Gh + (size_t)(pair & 7) * P * D;
    const int p0 = blockIdx.x * BM;

    const int tid  = threadIdx.x;
    const int lane = tid & 31;
    const int wid  = tid >> 5;
    const int wrow = (wid >> 2) * 64;  // warp m offset (0 / 64)
    const int wcol = (wid & 3) * 32;   // warp n offset (0..96)

    // loader mapping: thread -> (row = tid>>2 [+64], chunk = tid&3)
    const int lrow   = tid >> 2;  // 0..63
    const int lchunk = tid & 3;
    const uint32_t dA0 = swaddr(lrow, lchunk);
    const uint32_t dA1 = swaddr(lrow + 64, lchunk);

    float acc[4][4][4];
    float cmax[4][2];
    #pragma unroll
    for (int i = 0; i < 4; i++) { cmax[i][0] = -1e30f; cmax[i][1] = -1e30f; }
    #pragma unroll
    for (int i = 0; i < 4; i++)
        #pragma unroll
        for (int j = 0; j < 4; j++)
            #pragma unroll
            for (int e = 0; e < 4; e++) acc[i][j][e] = 0.f;

    // -------- cp.async tile loader for flattened step s --------
    auto load_step = [&](int s) {
        int q0 = (s / KSTEPS) * BN;
        int k0 = (s % KSTEPS) * BK;
        uint32_t Ab = sbase + (s % STAGES) * STAGE_BYTES;
        uint32_t Bb = Ab + TILE_BYTES;
        int ke = k0 + lchunk * 8;
        CPA16(Ab + dA0, Fb + ((size_t)(p0 + lrow) * D + ke));
        CPA16(Ab + dA1, Fb + ((size_t)(p0 + lrow + 64) * D + ke));
        CPA16(Bb + dA0, Gb + ((size_t)(q0 + lrow) * D + ke));
        CPA16(Bb + dA1, Gb + ((size_t)(q0 + lrow + 64) * D + ke));
    };

    // prologue
    #pragma unroll
    for (int s = 0; s < STAGES - 1; s++) {
        load_step(s);
        CPA_COMMIT();
    }

    // per-warp ldmatrix lane offsets
    const int mr = lane & 15;        // row-within-16 for ldsm
    const int cl = lane >> 4;        // 16B chunk select (0/1)

    int kc = 0;  // position within current q-pass
    for (int s = 0; s < NSTEP; s++) {
        CPA_WAIT1();
        __syncthreads();
        uint32_t Ab = sbase + (s % STAGES) * STAGE_BYTES;
        uint32_t Bb = Ab + TILE_BYTES;

        #pragma unroll
        for (int hk = 0; hk < 2; hk++) {
            uint32_t a[4][4], b[4][2];
            #pragma unroll
            for (int i = 0; i < 4; i++)
                ldsm4(a[i][0], a[i][1], a[i][2], a[i][3],
                      Ab + swaddr(wrow + i * 16 + mr, hk * 2 + cl));
            #pragma unroll
            for (int j = 0; j < 2; j++) {
                uint32_t r0, r1, r2, r3;
                ldsm4(r0, r1, r2, r3,
                      Bb + swaddr(wcol + j * 16 + mr, hk * 2 + cl));
                b[2 * j][0] = r0;     b[2 * j][1] = r2;
                b[2 * j + 1][0] = r1; b[2 * j + 1][1] = r3;
            }
            #pragma unroll
            for (int i = 0; i < 4; i++)
                #pragma unroll
                for (int j = 0; j < 4; j++)
                    mma16816(acc[i][j], a[i], b[j]);
        }

        // issue next stage (single __syncthreads per iter is sufficient:
        // target buffer was last read at step s-1, before the sync above)
        if (s + STAGES - 1 < NSTEP) load_step(s + STAGES - 1);
        CPA_COMMIT();

        if (++kc == KSTEPS) {  // end of a q-pass: fold max, reset acc
            kc = 0;
            #pragma unroll
            for (int i = 0; i < 4; i++) {
                float m0 = cmax[i][0], m1 = cmax[i][1];
                #pragma unroll
                for (int j = 0; j < 4; j++) {
                    m0 = fmaxf(m0, fmaxf(acc[i][j][0], acc[i][j][1]));
                    m1 = fmaxf(m1, fmaxf(acc[i][j][2], acc[i][j][3]));
                    acc[i][j][0] = 0.f; acc[i][j][1] = 0.f;
                    acc[i][j][2] = 0.f; acc[i][j][3] = 0.f;
                }
                cmax[i][0] = m0; cmax[i][1] = m1;
            }
        }
    }

    // reduce max over quad lanes (columns live in lane&3)
    #pragma unroll
    for (int i = 0; i < 4; i++) {
        #pragma unroll
        for (int e = 0; e < 2; e++) {
            float v = cmax[i][e];
            v = fmaxf(v, __shfl_xor_sync(0xffffffffu, v, 1));
            v = fmaxf(v, __shfl_xor_sync(0xffffffffu, v, 2));
            cmax[i][e] = v;
        }
    }

    __syncthreads();  // tiles dead; reuse smem for cross-warp max
    float* red = (float*)smem;  // [4 warp_cols][128 rows]
    if ((lane & 3) == 0) {
        int base = (wid & 3) * 128 + wrow;
        int r = lane >> 2;  // 0..7
        #pragma unroll
        for (int i = 0; i < 4; i++) {
            red[base + i * 16 + r]     = cmax[i][0];
            red[base + i * 16 + r + 8] = cmax[i][1];
        }
    }
    __syncthreads();
    if (tid < 128) {
        float v = red[tid];
        v = fmaxf(v, red[128 + tid]);
        v = fmaxf(v, red[256 + tid]);
        v = fmaxf(v, red[384 + tid]);
        float d2 = fmaxf(2.0f - 2.0f * v, 0.0f);
        g_spatch[(size_t)pair * P + p0 + tid] = 0.5f * sqrtf(d2);
    }
}

// ---------------------------------------------------------------------------
// Kernel 3: scores[n] = mean_m max_p spatch; sp[n][p] = mean_m spatch.
// ---------------------------------------------------------------------------
__global__ void reduce_k(float* __restrict__ scores) {
    const int n = blockIdx.x;
    const int p = threadIdx.x;
    float v[8];
    float s = 0.f;
    #pragma unroll
    for (int m = 0; m < 8; m++) {
        v[m] = g_spatch[(size_t)(n * 8 + m) * P + p];
        s += v[m];
    }
    g_sp[n * P + p] = s * 0.125f;

    __shared__ int smax[8];
    if (p < 8) smax[p] = 0;  // dist >= 0 so int-compare == float-compare
    __syncthreads();
    #pragma unroll
    for (int m = 0; m < 8; m++) {
        float x = v[m];
        #pragma unroll
        for (int off = 16; off; off >>= 1)
            x = fmaxf(x, __shfl_xor_sync(0xffffffffu, x, off));
        if ((p & 31) == 0) atomicMax(&smax[m], __float_as_int(x));
    }
    __syncthreads();
    if (p == 0) {
        float t = 0.f;
        #pragma unroll
        for (int m = 0; m < 8; m++) t += __int_as_float(smax[m]);
        scores[n] = t * 0.125f;
    }
}

// ---------------------------------------------------------------------------
// Kernel 4: bilinear resize (8,32,32) -> (8,512,512)
// ---------------------------------------------------------------------------
__global__ void resize_k(float* __restrict__ out) {
    int idx = blockIdx.x * blockDim.x + threadIdx.x;
    if (idx >= N1 * OH * OW) return;
    int c = idx & (OW - 1);
    int r = (idx >> 9) & (OH - 1);
    int n = idx >> 18;
    float sy = (r + 0.5f) * ((float)PH / OH) - 0.5f;
    float sx = (c + 0.5f) * ((float)PW / OW) - 0.5f;
    float y0f = floorf(sy), x0f = floorf(sx);
    float wy = sy - y0f, wx = sx - x0f;
    int y0 = min(max((int)y0f, 0), PH - 1);
    int y1 = min(max((int)y0f + 1, 0), PH - 1);
    int x0 = min(max((int)x0f, 0), PW - 1);
    int x1 = min(max((int)x0f + 1, 0), PW - 1);
    const float* __restrict__ b = g_sp + n * (PH * PW);
    float v00 = b[y0 * PW + x0], v01 = b[y0 * PW + x1];
    float v10 = b[y1 * PW + x0], v11 = b[y1 * PW + x1];
    float top = v00 * (1.f - wx) + v01 * wx;
    float bot = v10 * (1.f - wx) + v11 * wx;
    out[idx] = top * (1.f - wy) + bot * wy;
}

// ---------------------------------------------------------------------------
extern "C" void kernel_launch(void* const* d_in, const int* in_sizes, int n_in,
                              void* d_out, int out_size) {
    (void)in_sizes; (void)n_in; (void)out_size;
    const float* feats  = (const float*)d_in[0];
    const float* nfeats = (const float*)d_in[1];
    float* out = (float*)d_out;  // [0..7] = scores, [8..] = scores_pixel

    norm_k<<<(N1 + N2) * P, 192>>>(feats, nfeats);
    dim3 ggrid(P / BM, N1 * N2);
    gemm_max_k<<<ggrid, 256>>>();
    reduce_k<<<N1, P>>>(out);
    resize_k<<<(N1 * OH * OW + 255) / 256, 256>>>(out + N1);
}